// round 2
// baseline (speedup 1.0000x reference)
#include <cuda_runtime.h>
#include <math.h>

#define CH 64
#define MAX_NODES 50000
#define KS 128        // concat K dim: [x | buf]
#define NPB 64        // nodes per GEMM block
#define STR 65        // padded shared stride (bank-conflict mitigation)
#define SMEM_BYTES (2 * KS * STR * sizeof(float))

// Scratch for the scatter-accumulated, scaled source features.
__device__ float g_buf[MAX_NODES * CH];
// 1 if edge_index buffer is int64, 0 if int32 (probed on device each run).
__device__ int g_is64;

// ---------------------------------------------------------------------------
// Kernel 0: probe edge_index dtype. If int64 little-endian with values < 2^31,
// every odd 32-bit word of the buffer is zero. Random int32 indices make the
// all-zero pattern over 32 odd words impossible (~(2e-5)^32).
// ---------------------------------------------------------------------------
__global__ void probe_dtype_kernel(const int* __restrict__ ei32) {
    int is64 = 1;
    for (int i = 0; i < 32; i++) {
        if (ei32[2 * i + 1] != 0) { is64 = 0; break; }
    }
    g_is64 = is64;
}

// ---------------------------------------------------------------------------
// Kernel 1: zero the scratch accumulator (must happen every replay).
// ---------------------------------------------------------------------------
__global__ void zero_buf_kernel(int n4) {
    int i = blockIdx.x * blockDim.x + threadIdx.x;
    if (i < n4) {
        reinterpret_cast<float4*>(g_buf)[i] = make_float4(0.f, 0.f, 0.f, 0.f);
    }
}

// ---------------------------------------------------------------------------
// Kernel 2: edge scatter.
//   g_buf[dst] += ||edge_attr[e]|| * x[src]
// 16 threads per edge; each thread handles one float4 (4 channels).
// Leader lane loads indices + attr, broadcasts via shuffle.
// ---------------------------------------------------------------------------
__global__ void __launch_bounds__(256) edge_scatter_kernel(
    const float* __restrict__ x,
    const void* __restrict__ ei_raw,
    const float* __restrict__ ea,
    int E, int N)
{
    int t = blockIdx.x * blockDim.x + threadIdx.x;
    int e = t >> 4;
    if (e >= E) return;
    int lane = threadIdx.x & 15;
    int grpleader = threadIdx.x & 16;  // lane-in-warp of this 16-group's leader

    int src = 0, dst = 0;
    float scale = 0.f;
    if (lane == 0) {
        if (g_is64) {
            const long long* ei = (const long long*)ei_raw;
            src = (int)__ldg(&ei[e]);
            dst = (int)__ldg(&ei[E + e]);
        } else {
            const int* ei = (const int*)ei_raw;
            src = __ldg(&ei[e]);
            dst = __ldg(&ei[E + e]);
        }
        float a0 = __ldg(&ea[3 * e + 0]);
        float a1 = __ldg(&ea[3 * e + 1]);
        float a2 = __ldg(&ea[3 * e + 2]);
        scale = sqrtf(a0 * a0 + a1 * a1 + a2 * a2);
    }
    src   = __shfl_sync(0xffffffffu, src,   grpleader);
    dst   = __shfl_sync(0xffffffffu, dst,   grpleader);
    scale = __shfl_sync(0xffffffffu, scale, grpleader);

    // Bounds guard: never fault; wrong-dtype guess shows up as rel_err instead.
    if ((unsigned)src >= (unsigned)N || (unsigned)dst >= (unsigned)N) return;

    float4 v = __ldg(reinterpret_cast<const float4*>(x + (size_t)src * CH) + lane);
    v.x *= scale; v.y *= scale; v.z *= scale; v.w *= scale;

    float* addr = g_buf + (size_t)dst * CH + lane * 4;
    asm volatile("red.global.add.v4.f32 [%0], {%1, %2, %3, %4};"
                 :: "l"(addr), "f"(v.x), "f"(v.y), "f"(v.z), "f"(v.w)
                 : "memory");
}

// ---------------------------------------------------------------------------
// Kernel 3: fused GEMM
//   out[n, o] = sum_{i<64} x[n,i]*psi[o,i] + sum_{i<64} g_buf[n,i]*phi[o,i]
// Single K=128 GEMM with concatenated A = [x | g_buf], W = [psi ; phi].
// Shared tiles stored transposed (k-major) with stride 65.
// 256 threads: 4 nodes x 4 outputs per thread.
// ---------------------------------------------------------------------------
extern __shared__ float smem[];

__global__ void __launch_bounds__(256) fused_gemm_kernel(
    const float* __restrict__ x,
    const float* __restrict__ phi,
    const float* __restrict__ psi,
    float* __restrict__ out,
    int N)
{
    float* Ws = smem;               // Ws[i * STR + o], i in [0,128), o in [0,64)
    float* As = smem + KS * STR;    // As[i * STR + n], n in [0,NPB)
    int tid = threadIdx.x;

    // Stage weights: coalesced global reads (i fast), conflict-spread smem writes.
    for (int idx = tid; idx < CH * KS; idx += 256) {
        int o = idx >> 7;
        int i = idx & 127;
        float v = (i < CH) ? __ldg(&psi[o * CH + i])
                           : __ldg(&phi[o * CH + (i - CH)]);
        Ws[i * STR + o] = v;
    }

    int node0 = blockIdx.x * NPB;
    for (int idx = tid; idx < NPB * KS; idx += 256) {
        int n = idx >> 7;
        int i = idx & 127;
        int gn = node0 + n;
        float v = 0.f;
        if (gn < N) {
            v = (i < CH) ? __ldg(&x[(size_t)gn * CH + i])
                         : g_buf[(size_t)gn * CH + (i - CH)];
        }
        As[i * STR + n] = v;
    }
    __syncthreads();

    int tn = tid >> 4;     // 0..15 node group (broadcast a-loads)
    int to = tid & 15;     // 0..15 output group
    int nb = tn * 4;
    int ob = to * 4;

    float acc[4][4] = {};

    #pragma unroll 4
    for (int i = 0; i < KS; i++) {
        const float* ar = As + i * STR + nb;
        const float* wr = Ws + i * STR + ob;
        float a0 = ar[0], a1 = ar[1], a2 = ar[2], a3 = ar[3];
        float w0 = wr[0], w1 = wr[1], w2 = wr[2], w3 = wr[3];
        acc[0][0] += a0 * w0; acc[0][1] += a0 * w1; acc[0][2] += a0 * w2; acc[0][3] += a0 * w3;
        acc[1][0] += a1 * w0; acc[1][1] += a1 * w1; acc[1][2] += a1 * w2; acc[1][3] += a1 * w3;
        acc[2][0] += a2 * w0; acc[2][1] += a2 * w1; acc[2][2] += a2 * w2; acc[2][3] += a2 * w3;
        acc[3][0] += a3 * w0; acc[3][1] += a3 * w1; acc[3][2] += a3 * w2; acc[3][3] += a3 * w3;
    }

    #pragma unroll
    for (int kn = 0; kn < 4; kn++) {
        int gn = node0 + nb + kn;
        if (gn < N) {
            float* orow = out + (size_t)gn * CH + ob;
            #pragma unroll
            for (int ko = 0; ko < 4; ko++) {
                orow[ko] = acc[kn][ko];
            }
        }
    }
}

// ---------------------------------------------------------------------------
// Launch
// ---------------------------------------------------------------------------
extern "C" void kernel_launch(void* const* d_in, const int* in_sizes, int n_in,
                              void* d_out, int out_size) {
    const float* x   = (const float*)d_in[0];
    const void*  ei  = d_in[1];
    const float* ea  = (const float*)d_in[2];
    const float* phi = (const float*)d_in[3];
    const float* psi = (const float*)d_in[4];
    float*       out = (float*)d_out;

    int N = in_sizes[0] / CH;   // 50000
    int E = in_sizes[1] / 2;    // 800000

    // 0. probe edge_index dtype (reads first 256 bytes only — safe either way)
    probe_dtype_kernel<<<1, 1>>>((const int*)ei);

    // 1. zero accumulator
    int n4 = (N * CH) / 4;
    zero_buf_kernel<<<(n4 + 255) / 256, 256>>>(n4);

    // 2. edge scatter (16 threads per edge)
    long long tot = (long long)E * 16;
    int eblocks = (int)((tot + 255) / 256);
    edge_scatter_kernel<<<eblocks, 256>>>(x, ei, ea, E, N);

    // 3. fused GEMM: out = [x | g_buf] @ [psi ; phi]^T
    cudaFuncSetAttribute(fused_gemm_kernel,
                         cudaFuncAttributeMaxDynamicSharedMemorySize,
                         (int)SMEM_BYTES);
    fused_gemm_kernel<<<(N + NPB - 1) / NPB, 256, SMEM_BYTES>>>(x, phi, psi, out, N);
}

// round 3
// speedup vs baseline: 1.1522x; 1.1522x over previous
#include <cuda_runtime.h>
#include <math.h>

#define CH 64
#define MAX_NODES 50000
#define KS 128        // concat K dim: [x | g_buf]
#define NPB 128       // nodes per GEMM block
#define ASTR 129      // A tile stride (odd -> conflict-free columns)
#define WSTR 65       // W tile stride
#define GEMM_SMEM ((KS * ASTR + KS * WSTR) * (int)sizeof(float))  // 99328 B

// Scratch for the scatter-accumulated, scaled source features.
__device__ float g_buf[MAX_NODES * CH];
// 1 if edge_index buffer is int64, 0 if int32 (probed on device each run).
__device__ int g_is64;

// ---------------------------------------------------------------------------
// Kernel 0: probe edge_index dtype. int64 little-endian with values < 2^31
// => every odd 32-bit word zero. Random int32 can't produce 32 zeros.
// ---------------------------------------------------------------------------
__global__ void probe_dtype_kernel(const int* __restrict__ ei32) {
    int is64 = 1;
    for (int i = 0; i < 32; i++) {
        if (ei32[2 * i + 1] != 0) { is64 = 0; break; }
    }
    g_is64 = is64;
}

// ---------------------------------------------------------------------------
// Kernel 1: zero the scratch accumulator (every replay).
// ---------------------------------------------------------------------------
__global__ void zero_buf_kernel(int n4) {
    int i = blockIdx.x * blockDim.x + threadIdx.x;
    if (i < n4) {
        reinterpret_cast<float4*>(g_buf)[i] = make_float4(0.f, 0.f, 0.f, 0.f);
    }
}

// ---------------------------------------------------------------------------
// Kernel 2: edge scatter.  g_buf[dst] += ||edge_attr[e]|| * x[src]
// 16 threads per edge, one float4 per thread; leader loads metadata.
// ---------------------------------------------------------------------------
__global__ void __launch_bounds__(256) edge_scatter_kernel(
    const float* __restrict__ x,
    const void* __restrict__ ei_raw,
    const float* __restrict__ ea,
    int E, int N)
{
    int t = blockIdx.x * blockDim.x + threadIdx.x;
    int e = t >> 4;
    if (e >= E) return;
    int lane = threadIdx.x & 15;
    int grpleader = threadIdx.x & 16;

    int src = 0, dst = 0;
    float scale = 0.f;
    if (lane == 0) {
        if (g_is64) {
            const long long* ei = (const long long*)ei_raw;
            src = (int)__ldg(&ei[e]);
            dst = (int)__ldg(&ei[E + e]);
        } else {
            const int* ei = (const int*)ei_raw;
            src = __ldg(&ei[e]);
            dst = __ldg(&ei[E + e]);
        }
        float a0 = __ldg(&ea[3 * e + 0]);
        float a1 = __ldg(&ea[3 * e + 1]);
        float a2 = __ldg(&ea[3 * e + 2]);
        scale = sqrtf(a0 * a0 + a1 * a1 + a2 * a2);
    }
    src   = __shfl_sync(0xffffffffu, src,   grpleader);
    dst   = __shfl_sync(0xffffffffu, dst,   grpleader);
    scale = __shfl_sync(0xffffffffu, scale, grpleader);

    if ((unsigned)src >= (unsigned)N || (unsigned)dst >= (unsigned)N) return;

    float4 v = __ldg(reinterpret_cast<const float4*>(x + (size_t)src * CH) + lane);
    v.x *= scale; v.y *= scale; v.z *= scale; v.w *= scale;

    float* addr = g_buf + (size_t)dst * CH + lane * 4;
    asm volatile("red.global.add.v4.f32 [%0], {%1, %2, %3, %4};"
                 :: "l"(addr), "f"(v.x), "f"(v.y), "f"(v.z), "f"(v.w)
                 : "memory");
}

// ---------------------------------------------------------------------------
// Kernel 3: fused GEMM   out = [x | g_buf] @ [psi ; phi]^T
// Tile: 128 nodes x 64 outputs x K=128. 256 threads.
// Per thread: 4 nodes (strided tn+32j) x 8 outputs -> 32 accumulators.
// A in smem [k][n] stride 129 (conflict-free strided reads),
// W in smem [k][o] stride 65 (warp-broadcast reads).
// ---------------------------------------------------------------------------
extern __shared__ float smem[];

__global__ void __launch_bounds__(256) fused_gemm_kernel(
    const float* __restrict__ x,
    const float* __restrict__ phi,
    const float* __restrict__ psi,
    float* __restrict__ out,
    int N)
{
    float* As = smem;                 // As[k * ASTR + n]
    float* Ws = smem + KS * ASTR;     // Ws[k * WSTR + o]
    int tid = threadIdx.x;
    int node0 = blockIdx.x * NPB;

    // Stage W: [psi ; phi] -> Ws[i][o]; coalesced LDG, bank-step-1 STS.
    for (int idx = tid; idx < CH * KS; idx += 256) {
        int o = idx >> 7;
        int i = idx & 127;
        float v = (i < CH) ? __ldg(&psi[o * CH + i])
                           : __ldg(&phi[o * CH + (i - CH)]);
        Ws[i * WSTR + o] = v;
    }

    // Stage A: float4 LDG from x / g_buf, scalar STS transpose into [k][n].
    for (int idx4 = tid; idx4 < NPB * 32; idx4 += 256) {
        int n  = idx4 >> 5;        // node within tile
        int i4 = idx4 & 31;        // which float4 of the 128-float row
        int gn = node0 + n;
        float4 v = make_float4(0.f, 0.f, 0.f, 0.f);
        if (gn < N) {
            v = (i4 < 16)
                ? __ldg(reinterpret_cast<const float4*>(x + (size_t)gn * CH) + i4)
                : __ldg(reinterpret_cast<const float4*>(g_buf + (size_t)gn * CH) + (i4 - 16));
        }
        int i = i4 * 4;
        As[(i + 0) * ASTR + n] = v.x;
        As[(i + 1) * ASTR + n] = v.y;
        As[(i + 2) * ASTR + n] = v.z;
        As[(i + 3) * ASTR + n] = v.w;
    }
    __syncthreads();

    int tn = tid & 31;          // node lane: handles nodes tn, tn+32, tn+64, tn+96
    int ob = (tid >> 5) * 8;    // 8 consecutive outputs

    float acc[4][8];
    #pragma unroll
    for (int j = 0; j < 4; j++)
        #pragma unroll
        for (int o = 0; o < 8; o++) acc[j][o] = 0.f;

    #pragma unroll 2
    for (int k = 0; k < KS; k++) {
        const float* ar = As + k * ASTR + tn;
        const float* wr = Ws + k * WSTR + ob;
        float a[4], w[8];
        #pragma unroll
        for (int j = 0; j < 4; j++) a[j] = ar[32 * j];
        #pragma unroll
        for (int o = 0; o < 8; o++) w[o] = wr[o];
        #pragma unroll
        for (int j = 0; j < 4; j++)
            #pragma unroll
            for (int o = 0; o < 8; o++)
                acc[j][o] += a[j] * w[o];
    }

    // Output: 8 contiguous floats per node row -> two STG.128, full 32B sectors.
    #pragma unroll
    for (int j = 0; j < 4; j++) {
        int gn = node0 + tn + 32 * j;
        if (gn < N) {
            float4* orow = reinterpret_cast<float4*>(out + (size_t)gn * CH + ob);
            orow[0] = make_float4(acc[j][0], acc[j][1], acc[j][2], acc[j][3]);
            orow[1] = make_float4(acc[j][4], acc[j][5], acc[j][6], acc[j][7]);
        }
    }
}

// ---------------------------------------------------------------------------
// Launch
// ---------------------------------------------------------------------------
extern "C" void kernel_launch(void* const* d_in, const int* in_sizes, int n_in,
                              void* d_out, int out_size) {
    const float* x   = (const float*)d_in[0];
    const void*  ei  = d_in[1];
    const float* ea  = (const float*)d_in[2];
    const float* phi = (const float*)d_in[3];
    const float* psi = (const float*)d_in[4];
    float*       out = (float*)d_out;

    int N = in_sizes[0] / CH;   // 50000
    int E = in_sizes[1] / 2;    // 800000

    probe_dtype_kernel<<<1, 1>>>((const int*)ei);

    int n4 = (N * CH) / 4;
    zero_buf_kernel<<<(n4 + 255) / 256, 256>>>(n4);

    long long tot = (long long)E * 16;
    int eblocks = (int)((tot + 255) / 256);
    edge_scatter_kernel<<<eblocks, 256>>>(x, ei, ea, E, N);

    cudaFuncSetAttribute(fused_gemm_kernel,
                         cudaFuncAttributeMaxDynamicSharedMemorySize,
                         GEMM_SMEM);
    fused_gemm_kernel<<<(N + NPB - 1) / NPB, 256, GEMM_SMEM>>>(x, phi, psi, out, N);
}